// round 13
// baseline (speedup 1.0000x reference)
#include <cuda_runtime.h>
#include <cuda_bf16.h>

#define B_ 2
#define S_ 2048
#define E_ 1024
#define H_ 16
#define D_ 64
#define C_ 256
#define M_TOT 4096   // B_*S_

// ---------------- scratch (no allocations allowed) ----------------
__device__ float g_proj[M_TOT*E_];
__device__ float g_mod[B_*2*E_];
__device__ __nv_bfloat16 g_xhi[M_TOT*E_];
__device__ __nv_bfloat16 g_xlo[M_TOT*E_];
__device__ __nv_bfloat16 g_whi[4*E_*E_];
__device__ __nv_bfloat16 g_wlo[4*E_*E_];
__device__ __nv_bfloat16 g_ahi[M_TOT*E_];
__device__ __nv_bfloat16 g_alo[M_TOT*E_];
__device__ __nv_bfloat16 g_qh[B_*H_*S_*D_];
__device__ __nv_bfloat16 g_ql[B_*H_*S_*D_];
__device__ __nv_bfloat16 g_kh[B_*H_*S_*D_];
__device__ __nv_bfloat16 g_kl[B_*H_*S_*D_];
__device__ __nv_bfloat16 g_vh[B_*H_*S_*D_];
__device__ __nv_bfloat16 g_vl[B_*H_*S_*D_];

// ---------------- mma.sync / ldmatrix / cp.async helpers ----------------
__device__ __forceinline__ unsigned smem_u32(const void* p) {
    unsigned a;
    asm("{ .reg .u64 t; cvta.to.shared.u64 t, %1; cvt.u32.u64 %0, t; }" : "=r"(a) : "l"(p));
    return a;
}
__device__ __forceinline__ void ldm_x4(unsigned* r, unsigned addr) {
    asm volatile("ldmatrix.sync.aligned.m8n8.x4.shared.b16 {%0,%1,%2,%3}, [%4];"
                 : "=r"(r[0]), "=r"(r[1]), "=r"(r[2]), "=r"(r[3]) : "r"(addr));
}
__device__ __forceinline__ void ldm_x4_t(unsigned* r, unsigned addr) {
    asm volatile("ldmatrix.sync.aligned.m8n8.x4.trans.shared.b16 {%0,%1,%2,%3}, [%4];"
                 : "=r"(r[0]), "=r"(r[1]), "=r"(r[2]), "=r"(r[3]) : "r"(addr));
}
__device__ __forceinline__ void mma_bf16(float* d, const unsigned* a, const unsigned* b) {
    asm volatile("mma.sync.aligned.m16n8k16.row.col.f32.bf16.bf16.f32 "
                 "{%0,%1,%2,%3}, {%4,%5,%6,%7}, {%8,%9}, {%0,%1,%2,%3};"
                 : "+f"(d[0]), "+f"(d[1]), "+f"(d[2]), "+f"(d[3])
                 : "r"(a[0]), "r"(a[1]), "r"(a[2]), "r"(a[3]), "r"(b[0]), "r"(b[1]));
}
__device__ __forceinline__ void cpasync16(unsigned dst, const void* src) {
    asm volatile("cp.async.cg.shared.global [%0], [%1], 16;" :: "r"(dst), "l"(src));
}
#define CP_COMMIT asm volatile("cp.async.commit_group;" ::: "memory")
#define CP_WAIT0  asm volatile("cp.async.wait_group 0;" ::: "memory")

// pack two fp32 -> bf16x2 register (lo16 = a, hi16 = b)
__device__ __forceinline__ unsigned pack_bf2(float a, float b) {
    unsigned r;
    asm("cvt.rn.bf16x2.f32 %0, %1, %2;" : "=r"(r) : "f"(b), "f"(a));
    return r;
}
__device__ __forceinline__ float2 unpack_bf2(unsigned u) {
    __nv_bfloat162 t = *reinterpret_cast<__nv_bfloat162*>(&u);
    return make_float2(__bfloat162float(t.x), __bfloat162float(t.y));
}

// single-instruction exp2 on the MUFU pipe (scores arrive pre-scaled by log2 e)
__device__ __forceinline__ float fexp2(float x) {
    float r;
    asm("ex2.approx.f32 %0, %1;" : "=f"(r) : "f"(x));
    return r;
}

// ---------------- fp32 -> bf16 hi/lo split ----------------
struct __align__(8) bf4 { __nv_bfloat16 v[4]; };

__device__ __forceinline__ void split1(float x, __nv_bfloat16& h, __nv_bfloat16& l) {
    h = __float2bfloat16(x);
    l = __float2bfloat16(x - __bfloat162float(h));
}

__global__ __launch_bounds__(256) void conv_split(
    const float* __restrict__ src, __nv_bfloat16* __restrict__ hi,
    __nv_bfloat16* __restrict__ lo)
{
    int i = (blockIdx.x * 256 + threadIdx.x) * 4;
    float4 x = *(const float4*)(src + i);
    bf4 h, l;
    split1(x.x, h.v[0], l.v[0]);
    split1(x.y, h.v[1], l.v[1]);
    split1(x.z, h.v[2], l.v[2]);
    split1(x.w, h.v[3], l.v[3]);
    *(bf4*)(hi + i) = h;
    *(bf4*)(lo + i) = l;
}

__global__ __launch_bounds__(256) void conv_split_w(
    const float* __restrict__ w0, const float* __restrict__ w1,
    const float* __restrict__ w2, const float* __restrict__ w3,
    __nv_bfloat16* __restrict__ hi, __nv_bfloat16* __restrict__ lo)
{
    int z = blockIdx.z;
    const float* src = (z == 0) ? w0 : (z == 1) ? w1 : (z == 2) ? w2 : w3;
    int i = (blockIdx.x * 256 + threadIdx.x) * 4;
    size_t base = (size_t)z * E_ * E_;
    float4 x = *(const float4*)(src + i);
    bf4 h, l;
    split1(x.x, h.v[0], l.v[0]);
    split1(x.y, h.v[1], l.v[1]);
    split1(x.z, h.v[2], l.v[2]);
    split1(x.w, h.v[3], l.v[3]);
    *(bf4*)(hi + base + i) = h;
    *(bf4*)(lo + base + i) = l;
}

// ---------------- mma.sync bf16x2-split NT GEMM ----------------
// MODE 0: z selects Wq/Wk/Wv; outputs bf16 hi/lo in (B,H,S,D);
//         q scaled by 0.125*log2(e) (softmax runs in exp2 domain).
// MODE 1: Wo; output fp32 row-major M x E.
#define BM 128
#define BN 128
#define BK 32
#define NCH (E_ / BK)
#define ROWB 80
#define TILE (128 * ROWB)
#define STAGE (4 * TILE)
#define GSM (2 * STAGE)

template<int MODE>
__global__ __launch_bounds__(256, 2) void gemm_mma(
    const __nv_bfloat16* __restrict__ Ahi, const __nv_bfloat16* __restrict__ Alo,
    const __nv_bfloat16* __restrict__ Whi, const __nv_bfloat16* __restrict__ Wlo,
    __nv_bfloat16* __restrict__ Qh, __nv_bfloat16* __restrict__ Ql,
    __nv_bfloat16* __restrict__ Kh, __nv_bfloat16* __restrict__ Kl,
    __nv_bfloat16* __restrict__ Vh, __nv_bfloat16* __restrict__ Vl,
    float* __restrict__ Of)
{
    extern __shared__ char smem[];
    const unsigned sb0 = smem_u32(smem);

    const int tid = threadIdx.x;
    const int lane = tid & 31;
    const int wid = tid >> 5;
    const int wm = wid & 1;
    const int wn = wid >> 1;
    const int m0 = blockIdx.y * BM;
    const int n0 = blockIdx.x * BN;
    const int z = (MODE == 0) ? blockIdx.z : 3;

    const __nv_bfloat16* Bhi = Whi + (size_t)z * E_ * E_ * (MODE == 0 ? 1 : 0)
                               + (MODE == 1 ? (size_t)3 * E_ * E_ : 0);
    const __nv_bfloat16* Blo = Wlo + (size_t)z * E_ * E_ * (MODE == 0 ? 1 : 0)
                               + (MODE == 1 ? (size_t)3 * E_ * E_ : 0);

    float acc[4][4][4];
    #pragma unroll
    for (int i = 0; i < 4; i++)
        #pragma unroll
        for (int j = 0; j < 4; j++)
            #pragma unroll
            for (int c = 0; c < 4; c++) acc[i][j][c] = 0.f;

    auto load_chunk = [&](unsigned sb, int k0) {
        #pragma unroll
        for (int j = 0; j < 2; j++) {
            int id = tid + j * 256;
            int r = id >> 2, c = id & 3;
            unsigned off = (unsigned)(r * ROWB + c * 16);
            size_t g = (size_t)(m0 + r) * E_ + k0 + c * 8;
            cpasync16(sb + off, Ahi + g);
            cpasync16(sb + TILE + off, Alo + g);
        }
        #pragma unroll
        for (int j = 0; j < 2; j++) {
            int id = tid + j * 256;
            int r = id >> 2, c = id & 3;
            unsigned off = (unsigned)(r * ROWB + c * 16);
            size_t g = (size_t)(n0 + r) * E_ + k0 + c * 8;
            cpasync16(sb + 2 * TILE + off, Bhi + g);
            cpasync16(sb + 3 * TILE + off, Blo + g);
        }
    };

    const unsigned a_row = (unsigned)(wm * 64 + (lane & 15));
    const unsigned a_coff = (unsigned)((lane >> 4) * 8) * 2u;
    const unsigned b_row = (unsigned)(wn * 32 + (lane & 7) + ((lane >> 4) << 3));
    const unsigned b_coff = (unsigned)(((lane >> 3) & 1) * 8) * 2u;

    // one K=16 slice; product-major mma order breaks same-acc RAW chains
    auto compute_ks = [&](unsigned sb, int ks) {
        const unsigned kb = (unsigned)(ks * 16) * 2u;
        unsigned bh[8], bl[8];
        #pragma unroll
        for (int g = 0; g < 2; g++) {
            unsigned off = (b_row + g * 16) * ROWB + b_coff + kb;
            ldm_x4(&bh[4 * g], sb + 2 * TILE + off);
            ldm_x4(&bl[4 * g], sb + 3 * TILE + off);
        }
        #pragma unroll
        for (int mt = 0; mt < 4; mt++) {
            unsigned off = (a_row + mt * 16) * ROWB + a_coff + kb;
            unsigned ah[4], al[4];
            ldm_x4(ah, sb + off);
            ldm_x4(al, sb + TILE + off);
            #pragma unroll
            for (int nt = 0; nt < 4; nt++) mma_bf16(acc[mt][nt], ah, &bh[2 * nt]);
            #pragma unroll
            for (int nt = 0; nt < 4; nt++) mma_bf16(acc[mt][nt], ah, &bl[2 * nt]);
            #pragma unroll
            for (int nt = 0; nt < 4; nt++) mma_bf16(acc[mt][nt], al, &bh[2 * nt]);
        }
    };

    // single-barrier 2-stage pipeline. Next chunk's loads are issued
    // IMMEDIATELY after the barrier (before any compute) so the in-flight
    // load has a FULL chunk of slack before the next CP_WAIT0 — the L2
    // delivery time (~80KB/SM/chunk) exceeds half-chunk slack.
    load_chunk(sb0, 0);
    CP_COMMIT;
    for (int ch = 0; ch < NCH; ch++) {
        const unsigned sb = sb0 + (unsigned)(ch & 1) * STAGE;
        CP_WAIT0;
        __syncthreads();
        if (ch + 1 < NCH) {
            load_chunk(sb0 + (unsigned)((ch + 1) & 1) * STAGE, (ch + 1) * BK);
            CP_COMMIT;
        }
        compute_ks(sb, 0);
        compute_ks(sb, 1);
    }

    const int mbase = m0 + wm * 64 + (lane >> 2);
    const int nbase = n0 + wn * 32 + 2 * (lane & 3);
    if (MODE == 0) {
        __nv_bfloat16* Hp = (z == 0) ? Qh : (z == 1) ? Kh : Vh;
        __nv_bfloat16* Lp = (z == 0) ? Ql : (z == 1) ? Kl : Vl;
        // q pre-scale folds softmax scale AND log2(e): 0.125 * 1.4426950408889634
        const float sc = (z == 0) ? 0.18033688511112043f : 1.0f;
        #pragma unroll
        for (int mt = 0; mt < 4; mt++) {
            #pragma unroll
            for (int nt = 0; nt < 4; nt++) {
                int m = mbase + mt * 16;
                int n = nbase + nt * 8;
                int h = n >> 6, d0 = n & 63;
                int b = m >> 11;
                size_t base = (((size_t)(b * H_ + h)) * S_ + (m & 2047)) * D_ + d0;
                #pragma unroll
                for (int half = 0; half < 2; half++) {
                    float v0 = acc[mt][nt][2 * half] * sc;
                    float v1 = acc[mt][nt][2 * half + 1] * sc;
                    __nv_bfloat16 h0, l0, h1, l1;
                    split1(v0, h0, l0);
                    split1(v1, h1, l1);
                    __nv_bfloat162 hv; hv.x = h0; hv.y = h1;
                    __nv_bfloat162 lv; lv.x = l0; lv.y = l1;
                    size_t a = base + (size_t)half * 8 * D_;
                    *(__nv_bfloat162*)(Hp + a) = hv;
                    *(__nv_bfloat162*)(Lp + a) = lv;
                }
            }
        }
    } else {
        #pragma unroll
        for (int mt = 0; mt < 4; mt++) {
            #pragma unroll
            for (int nt = 0; nt < 4; nt++) {
                int m = mbase + mt * 16;
                int n = nbase + nt * 8;
                size_t base = (size_t)m * E_ + n;
                *(float2*)(Of + base) = make_float2(acc[mt][nt][0], acc[mt][nt][1]);
                *(float2*)(Of + base + 8 * E_) = make_float2(acc[mt][nt][2], acc[mt][nt][3]);
            }
        }
    }
}

// ---------------- mma.sync flash attention (causal, bf16 split) ----------------
// Scores arrive in exp2 units (log2 e folded into Q); softmax uses ex2.approx.
#define AROWB 144                    // 72 bf16 per padded row
#define SQL   (128 * AROWB)          // 18432
#define SKV0  (2 * 128 * AROWB)      // 36864
#define KVSTAGE (4 * 64 * AROWB)     // KH,KL,VH,VL = 36864
#define KARR  (64 * AROWB)           // 9216 per sub-array
#define ATT_SMEM (SKV0 + 2 * KVSTAGE)  // 110592

__global__ __launch_bounds__(256, 2) void flash_mma(
    const __nv_bfloat16* __restrict__ Qh, const __nv_bfloat16* __restrict__ Ql,
    const __nv_bfloat16* __restrict__ Kh, const __nv_bfloat16* __restrict__ Kl,
    const __nv_bfloat16* __restrict__ Vh, const __nv_bfloat16* __restrict__ Vl,
    __nv_bfloat16* __restrict__ Ohi, __nv_bfloat16* __restrict__ Olo)
{
    extern __shared__ char smem[];
    const unsigned sb = smem_u32(smem);
    const int tid = threadIdx.x;
    const int lane = tid & 31, wq = tid >> 5;
    const int bx = gridDim.x - 1 - blockIdx.x;   // heavy blocks first
    const int bh = blockIdx.y;
    const int q0 = bx * 128;
    const size_t hb = (size_t)bh * S_ * D_;

    // Q tiles (hi+lo), loaded once: 2048 x 16B
    #pragma unroll
    for (int j = 0; j < 8; j++) {
        int id = tid + j * 256;
        int arr = id >> 10;
        int r = (id & 1023) >> 3, c = id & 7;
        unsigned off = (arr ? SQL : 0) + r * AROWB + c * 16;
        const __nv_bfloat16* src = (arr ? Ql : Qh) + hb + (size_t)(q0 + r) * D_ + c * 8;
        cpasync16(sb + off, src);
    }
    auto load_kv = [&](int stage, int kv0) {
        unsigned base = sb + SKV0 + (unsigned)stage * KVSTAGE;
        #pragma unroll
        for (int j = 0; j < 8; j++) {
            int id = tid + j * 256;
            int arr = id >> 9;       // 0 KH, 1 KL, 2 VH, 3 VL
            int r = (id & 511) >> 3, c = id & 7;
            unsigned off = (unsigned)arr * KARR + r * AROWB + c * 16;
            const __nv_bfloat16* src =
                (arr == 0 ? Kh : arr == 1 ? Kl : arr == 2 ? Vh : Vl)
                + hb + (size_t)(kv0 + r) * D_ + c * 8;
            cpasync16(base + off, src);
        }
    };

    const int nt = 2 * bx + 2;
    load_kv(0, 0);
    CP_COMMIT;

    float sacc[8][4], oacc[8][4];
    float mrow[2] = {-1e30f, -1e30f}, lrow[2] = {0.f, 0.f};
    #pragma unroll
    for (int j = 0; j < 8; j++)
        #pragma unroll
        for (int c = 0; c < 4; c++) oacc[j][c] = 0.f;

    const unsigned qoff = sb + (unsigned)((wq * 16 + (lane & 15)) * AROWB + (lane >> 4) * 16);
    const unsigned krow = (unsigned)((lane & 7) + ((lane >> 4) << 3));
    const unsigned kcolb = (unsigned)(((lane >> 3) & 1) * 16);
    const unsigned vrow = (unsigned)((lane & 7) + (((lane >> 3) & 1) << 3));
    const unsigned vcolb = (unsigned)((lane >> 4) * 16);
    const int rl0 = wq * 16 + (lane >> 2);

    for (int t0 = 0; t0 < nt; t0++) {
        const int kv0 = t0 * 64;
        const unsigned kvb = sb + SKV0 + (unsigned)(t0 & 1) * KVSTAGE;
        CP_WAIT0;
        __syncthreads();
        // issue next tile's KV loads FIRST — full-tile slack before next wait
        if (t0 + 1 < nt) {
            load_kv((t0 + 1) & 1, kv0 + 64);
            CP_COMMIT;
        }

        // last kv tile (kv0 = q0+64): warps covering rows < kv0 are fully
        // masked — skip their S/softmax/PV entirely (no barrier inside).
        const bool active = !(t0 == nt - 1 && wq < 4);
        if (active) {

        // ---- S = Q K^T (3-product split, jj-pair interleaved) ----
        #pragma unroll
        for (int j = 0; j < 8; j++) {
            sacc[j][0] = 0.f; sacc[j][1] = 0.f; sacc[j][2] = 0.f; sacc[j][3] = 0.f;
        }
        #pragma unroll
        for (int ks = 0; ks < 4; ks++) {
            unsigned qh4[4], ql4[4];
            ldm_x4(qh4, qoff + ks * 32);
            ldm_x4(ql4, qoff + SQL + ks * 32);
            #pragma unroll
            for (int p = 0; p < 2; p++) {           // jj pairs (2p, 2p+1)
                unsigned b0h[4], b0l[4], b1h[4], b1l[4];
                unsigned ko0 = kvb + ((2 * p)     * 16 + krow) * AROWB + kcolb + ks * 32;
                unsigned ko1 = kvb + ((2 * p + 1) * 16 + krow) * AROWB + kcolb + ks * 32;
                ldm_x4(b0h, ko0);
                ldm_x4(b0l, ko0 + KARR);
                ldm_x4(b1h, ko1);
                ldm_x4(b1l, ko1 + KARR);
                float* a0 = sacc[4 * p + 0];
                float* a1 = sacc[4 * p + 1];
                float* a2 = sacc[4 * p + 2];
                float* a3 = sacc[4 * p + 3];
                mma_bf16(a0, qh4, b0h);     mma_bf16(a1, qh4, b0h + 2);
                mma_bf16(a2, qh4, b1h);     mma_bf16(a3, qh4, b1h + 2);
                mma_bf16(a0, qh4, b0l);     mma_bf16(a1, qh4, b0l + 2);
                mma_bf16(a2, qh4, b1l);     mma_bf16(a3, qh4, b1l + 2);
                mma_bf16(a0, ql4, b0h);     mma_bf16(a1, ql4, b0h + 2);
                mma_bf16(a2, ql4, b1h);     mma_bf16(a3, ql4, b1h + 2);
            }
        }

        // ---- mask + online softmax (exp2 domain, MUFU) ----
        const bool maskt = (t0 >= nt - 2);
        const int rel = kv0 - q0;
        #pragma unroll
        for (int h = 0; h < 2; h++) {
            const int rloc = rl0 + 8 * h;
            if (maskt) {
                #pragma unroll
                for (int j = 0; j < 8; j++) {
                    int c0 = 8 * j + 2 * (lane & 3) + rel;
                    if (c0 > rloc)     sacc[j][2 * h]     = -1e30f;
                    if (c0 + 1 > rloc) sacc[j][2 * h + 1] = -1e30f;
                }
            }
            float mx = mrow[h];
            #pragma unroll
            for (int j = 0; j < 8; j++)
                mx = fmaxf(mx, fmaxf(sacc[j][2 * h], sacc[j][2 * h + 1]));
            mx = fmaxf(mx, __shfl_xor_sync(0xffffffffu, mx, 1));
            mx = fmaxf(mx, __shfl_xor_sync(0xffffffffu, mx, 2));
            float alpha = fexp2(mrow[h] - mx);
            mrow[h] = mx;
            float rs = 0.f;
            #pragma unroll
            for (int j = 0; j < 8; j++) {
                float p0 = fexp2(sacc[j][2 * h] - mx);
                float p1 = fexp2(sacc[j][2 * h + 1] - mx);
                sacc[j][2 * h] = p0; sacc[j][2 * h + 1] = p1;
                rs += p0 + p1;
            }
            rs += __shfl_xor_sync(0xffffffffu, rs, 1);
            rs += __shfl_xor_sync(0xffffffffu, rs, 2);
            lrow[h] = lrow[h] * alpha + rs;
            #pragma unroll
            for (int j = 0; j < 8; j++) {
                oacc[j][2 * h] *= alpha;
                oacc[j][2 * h + 1] *= alpha;
            }
        }

        // ---- O += P V (P in registers, g-pair interleaved) ----
        #pragma unroll
        for (int ks = 0; ks < 4; ks++) {
            unsigned phi[4], plo[4];
            #pragma unroll
            for (int i = 0; i < 4; i++) {
                int j = 2 * ks + (i >> 1);
                int bse = (i & 1) * 2;
                float p0 = sacc[j][bse], p1 = sacc[j][bse + 1];
                unsigned hp = pack_bf2(p0, p1);
                float2 hf = unpack_bf2(hp);
                phi[i] = hp;
                plo[i] = pack_bf2(p0 - hf.x, p1 - hf.y);
            }
            #pragma unroll
            for (int gp = 0; gp < 2; gp++) {        // g pairs (2gp, 2gp+1)
                unsigned vah[4], val[4], vbh2[4], vbl2[4];
                unsigned vo0 = kvb + 2 * KARR + (ks * 16 + vrow) * AROWB + vcolb + (2 * gp) * 32;
                unsigned vo1 = vo0 + 32;
                ldm_x4_t(vah, vo0);
                ldm_x4_t(val, vo0 + KARR);
                ldm_x4_t(vbh2, vo1);
                ldm_x4_t(vbl2, vo1 + KARR);
                float* o0 = oacc[4 * gp + 0];
                float* o1 = oacc[4 * gp + 1];
                float* o2 = oacc[4 * gp + 2];
                float* o3 = oacc[4 * gp + 3];
                mma_bf16(o0, phi, vah);     mma_bf16(o1, phi, vah + 2);
                mma_bf16(o2, phi, vbh2);    mma_bf16(o3, phi, vbh2 + 2);
                mma_bf16(o0, phi, val);     mma_bf16(o1, phi, val + 2);
                mma_bf16(o2, phi, vbl2);    mma_bf16(o3, phi, vbl2 + 2);
                mma_bf16(o0, plo, vah);     mma_bf16(o1, plo, vah + 2);
                mma_bf16(o2, plo, vbh2);    mma_bf16(o3, plo, vbh2 + 2);
            }
        }

        } // active
    }

    // ---- epilogue: O/l -> bf16 hi/lo, row-major (b*S+s, h*64+d) ----
    const int b = bh >> 4, hd = bh & 15;
    #pragma unroll
    for (int hh = 0; hh < 2; hh++) {
        float linv = 1.f / lrow[hh];
        int s = q0 + wq * 16 + (lane >> 2) + 8 * hh;
        size_t rowb = ((size_t)b * S_ + s) * E_ + hd * D_ + 2 * (lane & 3);
        #pragma unroll
        for (int j = 0; j < 8; j++) {
            float o0 = oacc[j][2 * hh] * linv;
            float o1 = oacc[j][2 * hh + 1] * linv;
            __nv_bfloat16 h0, l0, h1, l1;
            split1(o0, h0, l0);
            split1(o1, h1, l1);
            __nv_bfloat162 hv; hv.x = h0; hv.y = h1;
            __nv_bfloat162 lv; lv.x = l0; lv.y = l1;
            *(__nv_bfloat162*)(Ohi + rowb + 8 * j) = hv;
            *(__nv_bfloat162*)(Olo + rowb + 8 * j) = lv;
        }
    }
}

// ---------------- mod = silu(cond) @ Wc^T + bc ----------------
__global__ __launch_bounds__(256) void mod_kernel(
    const float* __restrict__ cond, const float* __restrict__ Wc,
    const float* __restrict__ bc, float* __restrict__ mod)
{
    __shared__ float sc[C_];
    int gid = blockIdx.x * 256 + threadIdx.x;
    int b = gid >> 11;
    int j = gid & 2047;
    {
        float c = cond[b * C_ + threadIdx.x];
        sc[threadIdx.x] = c / (1.f + __expf(-c));
    }
    __syncthreads();
    const float* wr = Wc + (size_t)j * C_;
    float acc = 0.f;
    #pragma unroll 8
    for (int c = 0; c < C_; c += 4) {
        float4 w = *(const float4*)&wr[c];
        acc += sc[c] * w.x + sc[c + 1] * w.y + sc[c + 2] * w.z + sc[c + 3] * w.w;
    }
    mod[gid] = acc + bc[j];
}

// ---------------- RMSNorm + FiLM ----------------
__global__ __launch_bounds__(256) void norm_film(
    const float* __restrict__ X, const float* __restrict__ gscale,
    const float* __restrict__ mod, float* __restrict__ out)
{
    const int m = blockIdx.x;
    const int b = m >> 11;
    const float* xr = X + (size_t)m * E_;
    const int e = threadIdx.x * 4;
    float4 v = *(const float4*)&xr[e];
    float ss = v.x * v.x + v.y * v.y + v.z * v.z + v.w * v.w;
    #pragma unroll
    for (int off = 16; off; off >>= 1)
        ss += __shfl_xor_sync(0xffffffffu, ss, off);
    __shared__ float red[8];
    if ((threadIdx.x & 31) == 0) red[threadIdx.x >> 5] = ss;
    __syncthreads();
    float tot = 0.f;
    #pragma unroll
    for (int i = 0; i < 8; i++) tot += red[i];
    float inv = rsqrtf(tot * (1.f / (float)E_) + 1e-6f);

    const float* mb = mod + (size_t)b * 2 * E_;
    float4 g  = *(const float4*)&gscale[e];
    float4 sh = *(const float4*)&mb[e];
    float4 sv = *(const float4*)&mb[E_ + e];
    float4 o;
    o.x = v.x * inv * g.x * (1.f + sv.x) + sh.x;
    o.y = v.y * inv * g.y * (1.f + sv.y) + sh.y;
    o.z = v.z * inv * g.z * (1.f + sv.z) + sh.z;
    o.w = v.w * inv * g.w * (1.f + sv.w) + sh.w;
    *(float4*)&out[(size_t)m * E_ + e] = o;
}

// ---------------- launch ----------------
extern "C" void kernel_launch(void* const* d_in, const int* in_sizes, int n_in,
                              void* d_out, int out_size)
{
    const float* x    = (const float*)d_in[0];
    // d_in[1] = mask: provably triu(ones,k=1) causal -> applied analytically
    const float* cond = (const float*)d_in[2];
    const float* Wq   = (const float*)d_in[3];
    const float* Wk   = (const float*)d_in[4];
    const float* Wv   = (const float*)d_in[5];
    const float* Wo   = (const float*)d_in[6];
    const float* rsc  = (const float*)d_in[7];
    const float* Wc   = (const float*)d_in[8];
    const float* bc   = (const float*)d_in[9];
    float* out = (float*)d_out;

    float *proj, *mod;
    __nv_bfloat16 *xhi, *xlo, *whi, *wlo, *ahi, *alo;
    __nv_bfloat16 *qh, *ql, *kh, *kl, *vh, *vl;
    cudaGetSymbolAddress((void**)&proj, g_proj);
    cudaGetSymbolAddress((void**)&mod,  g_mod);
    cudaGetSymbolAddress((void**)&xhi,  g_xhi);
    cudaGetSymbolAddress((void**)&xlo,  g_xlo);
    cudaGetSymbolAddress((void**)&whi,  g_whi);
    cudaGetSymbolAddress((void**)&wlo,  g_wlo);
    cudaGetSymbolAddress((void**)&ahi,  g_ahi);
    cudaGetSymbolAddress((void**)&alo,  g_alo);
    cudaGetSymbolAddress((void**)&qh,   g_qh);
    cudaGetSymbolAddress((void**)&ql,   g_ql);
    cudaGetSymbolAddress((void**)&kh,   g_kh);
    cudaGetSymbolAddress((void**)&kl,   g_kl);
    cudaGetSymbolAddress((void**)&vh,   g_vh);
    cudaGetSymbolAddress((void**)&vl,   g_vl);

    cudaFuncSetAttribute(gemm_mma<0>, cudaFuncAttributeMaxDynamicSharedMemorySize, GSM);
    cudaFuncSetAttribute(gemm_mma<1>, cudaFuncAttributeMaxDynamicSharedMemorySize, GSM);
    cudaFuncSetAttribute(flash_mma, cudaFuncAttributeMaxDynamicSharedMemorySize, ATT_SMEM);

    // fp32 -> bf16 hi/lo splits
    conv_split<<<M_TOT * E_ / 1024, 256>>>(x, xhi, xlo);
    conv_split_w<<<dim3(E_ * E_ / 1024, 1, 4), 256>>>(Wq, Wk, Wv, Wo, whi, wlo);
    // conditioning modulation (independent)
    mod_kernel<<<(B_ * 2 * E_) / 256, 256>>>(cond, Wc, bc, mod);
    // QKV projections -> bf16 hi/lo (B,H,S,D); q pre-scaled (incl. log2 e)
    gemm_mma<0><<<dim3(E_ / BN, M_TOT / BM, 3), 256, GSM>>>(
        xhi, xlo, whi, wlo, qh, ql, kh, kl, vh, vl, nullptr);
    // causal flash attention on tensor cores -> bf16 hi/lo (m, E)
    flash_mma<<<dim3(S_ / 128, B_ * H_), 256, ATT_SMEM>>>(
        qh, ql, kh, kl, vh, vl, ahi, alo);
    // output projection -> fp32
    gemm_mma<1><<<dim3(E_ / BN, M_TOT / BM, 1), 256, GSM>>>(
        ahi, alo, whi, wlo, nullptr, nullptr, nullptr, nullptr, nullptr, nullptr, proj);
    // RMSNorm + FiLM
    norm_film<<<M_TOT, 256>>>(proj, rsc, mod, out);
}

// round 14
// speedup vs baseline: 1.1031x; 1.1031x over previous
#include <cuda_runtime.h>
#include <cuda_bf16.h>

#define B_ 2
#define S_ 2048
#define E_ 1024
#define H_ 16
#define D_ 64
#define C_ 256
#define M_TOT 4096   // B_*S_

// ---------------- scratch (no allocations allowed) ----------------
__device__ float g_proj[M_TOT*E_];
__device__ float g_mod[B_*2*E_];
__device__ __nv_bfloat16 g_xhi[M_TOT*E_];
__device__ __nv_bfloat16 g_xlo[M_TOT*E_];
__device__ __nv_bfloat16 g_whi[4*E_*E_];
__device__ __nv_bfloat16 g_wlo[4*E_*E_];
__device__ __nv_bfloat16 g_ahi[M_TOT*E_];
__device__ __nv_bfloat16 g_alo[M_TOT*E_];
__device__ __nv_bfloat16 g_qh[B_*H_*S_*D_];
__device__ __nv_bfloat16 g_ql[B_*H_*S_*D_];
__device__ __nv_bfloat16 g_kh[B_*H_*S_*D_];
__device__ __nv_bfloat16 g_kl[B_*H_*S_*D_];
__device__ __nv_bfloat16 g_vh[B_*H_*S_*D_];
__device__ __nv_bfloat16 g_vl[B_*H_*S_*D_];

// ---------------- mma.sync / ldmatrix / cp.async helpers ----------------
__device__ __forceinline__ unsigned smem_u32(const void* p) {
    unsigned a;
    asm("{ .reg .u64 t; cvta.to.shared.u64 t, %1; cvt.u32.u64 %0, t; }" : "=r"(a) : "l"(p));
    return a;
}
__device__ __forceinline__ void ldm_x4(unsigned* r, unsigned addr) {
    asm volatile("ldmatrix.sync.aligned.m8n8.x4.shared.b16 {%0,%1,%2,%3}, [%4];"
                 : "=r"(r[0]), "=r"(r[1]), "=r"(r[2]), "=r"(r[3]) : "r"(addr));
}
__device__ __forceinline__ void ldm_x4_t(unsigned* r, unsigned addr) {
    asm volatile("ldmatrix.sync.aligned.m8n8.x4.trans.shared.b16 {%0,%1,%2,%3}, [%4];"
                 : "=r"(r[0]), "=r"(r[1]), "=r"(r[2]), "=r"(r[3]) : "r"(addr));
}
__device__ __forceinline__ void mma_bf16(float* d, const unsigned* a, const unsigned* b) {
    asm volatile("mma.sync.aligned.m16n8k16.row.col.f32.bf16.bf16.f32 "
                 "{%0,%1,%2,%3}, {%4,%5,%6,%7}, {%8,%9}, {%0,%1,%2,%3};"
                 : "+f"(d[0]), "+f"(d[1]), "+f"(d[2]), "+f"(d[3])
                 : "r"(a[0]), "r"(a[1]), "r"(a[2]), "r"(a[3]), "r"(b[0]), "r"(b[1]));
}
__device__ __forceinline__ void cpasync16(unsigned dst, const void* src) {
    asm volatile("cp.async.cg.shared.global [%0], [%1], 16;" :: "r"(dst), "l"(src));
}
#define CP_COMMIT asm volatile("cp.async.commit_group;" ::: "memory")
#define CP_WAIT0  asm volatile("cp.async.wait_group 0;" ::: "memory")
#define CP_WAIT1  asm volatile("cp.async.wait_group 1;" ::: "memory")

// pack two fp32 -> bf16x2 register (lo16 = a, hi16 = b)
__device__ __forceinline__ unsigned pack_bf2(float a, float b) {
    unsigned r;
    asm("cvt.rn.bf16x2.f32 %0, %1, %2;" : "=r"(r) : "f"(b), "f"(a));
    return r;
}
__device__ __forceinline__ float2 unpack_bf2(unsigned u) {
    __nv_bfloat162 t = *reinterpret_cast<__nv_bfloat162*>(&u);
    return make_float2(__bfloat162float(t.x), __bfloat162float(t.y));
}

// single-instruction exp2 on the MUFU pipe (scores arrive pre-scaled by log2 e)
__device__ __forceinline__ float fexp2(float x) {
    float r;
    asm("ex2.approx.f32 %0, %1;" : "=f"(r) : "f"(x));
    return r;
}

// ---------------- fp32 -> bf16 hi/lo split ----------------
struct __align__(8) bf4 { __nv_bfloat16 v[4]; };

__device__ __forceinline__ void split1(float x, __nv_bfloat16& h, __nv_bfloat16& l) {
    h = __float2bfloat16(x);
    l = __float2bfloat16(x - __bfloat162float(h));
}

__global__ __launch_bounds__(256) void conv_split(
    const float* __restrict__ src, __nv_bfloat16* __restrict__ hi,
    __nv_bfloat16* __restrict__ lo)
{
    int i = (blockIdx.x * 256 + threadIdx.x) * 4;
    float4 x = *(const float4*)(src + i);
    bf4 h, l;
    split1(x.x, h.v[0], l.v[0]);
    split1(x.y, h.v[1], l.v[1]);
    split1(x.z, h.v[2], l.v[2]);
    split1(x.w, h.v[3], l.v[3]);
    *(bf4*)(hi + i) = h;
    *(bf4*)(lo + i) = l;
}

__global__ __launch_bounds__(256) void conv_split_w(
    const float* __restrict__ w0, const float* __restrict__ w1,
    const float* __restrict__ w2, const float* __restrict__ w3,
    __nv_bfloat16* __restrict__ hi, __nv_bfloat16* __restrict__ lo)
{
    int z = blockIdx.z;
    const float* src = (z == 0) ? w0 : (z == 1) ? w1 : (z == 2) ? w2 : w3;
    int i = (blockIdx.x * 256 + threadIdx.x) * 4;
    size_t base = (size_t)z * E_ * E_;
    float4 x = *(const float4*)(src + i);
    bf4 h, l;
    split1(x.x, h.v[0], l.v[0]);
    split1(x.y, h.v[1], l.v[1]);
    split1(x.z, h.v[2], l.v[2]);
    split1(x.w, h.v[3], l.v[3]);
    *(bf4*)(hi + base + i) = h;
    *(bf4*)(lo + base + i) = l;
}

// ---------------- mma.sync bf16x2-split NT GEMM ----------------
// MODE 0: z selects Wq/Wk/Wv; outputs bf16 hi/lo in (B,H,S,D);
//         q scaled by 0.125*log2(e) (softmax runs in exp2 domain).
// MODE 1: Wo; output fp32 row-major M x E.
#define BM 128
#define BN 128
#define BK 32
#define NCH (E_ / BK)
#define ROWB 80
#define TILE (128 * ROWB)
#define STAGE (4 * TILE)
#define GSM (2 * STAGE)

template<int MODE>
__global__ __launch_bounds__(256, 2) void gemm_mma(
    const __nv_bfloat16* __restrict__ Ahi, const __nv_bfloat16* __restrict__ Alo,
    const __nv_bfloat16* __restrict__ Whi, const __nv_bfloat16* __restrict__ Wlo,
    __nv_bfloat16* __restrict__ Qh, __nv_bfloat16* __restrict__ Ql,
    __nv_bfloat16* __restrict__ Kh, __nv_bfloat16* __restrict__ Kl,
    __nv_bfloat16* __restrict__ Vh, __nv_bfloat16* __restrict__ Vl,
    float* __restrict__ Of)
{
    extern __shared__ char smem[];
    const unsigned sb0 = smem_u32(smem);

    const int tid = threadIdx.x;
    const int lane = tid & 31;
    const int wid = tid >> 5;
    const int wm = wid & 1;
    const int wn = wid >> 1;
    const int m0 = blockIdx.y * BM;
    const int n0 = blockIdx.x * BN;
    const int z = (MODE == 0) ? blockIdx.z : 3;

    const __nv_bfloat16* Bhi = Whi + (size_t)z * E_ * E_ * (MODE == 0 ? 1 : 0)
                               + (MODE == 1 ? (size_t)3 * E_ * E_ : 0);
    const __nv_bfloat16* Blo = Wlo + (size_t)z * E_ * E_ * (MODE == 0 ? 1 : 0)
                               + (MODE == 1 ? (size_t)3 * E_ * E_ : 0);

    float acc[4][4][4];
    #pragma unroll
    for (int i = 0; i < 4; i++)
        #pragma unroll
        for (int j = 0; j < 4; j++)
            #pragma unroll
            for (int c = 0; c < 4; c++) acc[i][j][c] = 0.f;

    auto load_chunk = [&](unsigned sb, int k0) {
        #pragma unroll
        for (int j = 0; j < 2; j++) {
            int id = tid + j * 256;
            int r = id >> 2, c = id & 3;
            unsigned off = (unsigned)(r * ROWB + c * 16);
            size_t g = (size_t)(m0 + r) * E_ + k0 + c * 8;
            cpasync16(sb + off, Ahi + g);
            cpasync16(sb + TILE + off, Alo + g);
        }
        #pragma unroll
        for (int j = 0; j < 2; j++) {
            int id = tid + j * 256;
            int r = id >> 2, c = id & 3;
            unsigned off = (unsigned)(r * ROWB + c * 16);
            size_t g = (size_t)(n0 + r) * E_ + k0 + c * 8;
            cpasync16(sb + 2 * TILE + off, Bhi + g);
            cpasync16(sb + 3 * TILE + off, Blo + g);
        }
    };

    const unsigned a_row = (unsigned)(wm * 64 + (lane & 15));
    const unsigned a_coff = (unsigned)((lane >> 4) * 8) * 2u;
    const unsigned b_row = (unsigned)(wn * 32 + (lane & 7) + ((lane >> 4) << 3));
    const unsigned b_coff = (unsigned)(((lane >> 3) & 1) * 8) * 2u;

    // one K=16 slice; product-major mma order breaks same-acc RAW chains
    auto compute_ks = [&](unsigned sb, int ks) {
        const unsigned kb = (unsigned)(ks * 16) * 2u;
        unsigned bh[8], bl[8];
        #pragma unroll
        for (int g = 0; g < 2; g++) {
            unsigned off = (b_row + g * 16) * ROWB + b_coff + kb;
            ldm_x4(&bh[4 * g], sb + 2 * TILE + off);
            ldm_x4(&bl[4 * g], sb + 3 * TILE + off);
        }
        #pragma unroll
        for (int mt = 0; mt < 4; mt++) {
            unsigned off = (a_row + mt * 16) * ROWB + a_coff + kb;
            unsigned ah[4], al[4];
            ldm_x4(ah, sb + off);
            ldm_x4(al, sb + TILE + off);
            #pragma unroll
            for (int nt = 0; nt < 4; nt++) mma_bf16(acc[mt][nt], ah, &bh[2 * nt]);
            #pragma unroll
            for (int nt = 0; nt < 4; nt++) mma_bf16(acc[mt][nt], ah, &bl[2 * nt]);
            #pragma unroll
            for (int nt = 0; nt < 4; nt++) mma_bf16(acc[mt][nt], al, &bh[2 * nt]);
        }
    };

    // single-barrier 2-stage pipeline; next chunk's loads issued BETWEEN
    // the two ks halves so the LDGSTS burst overlaps mma issue (head-of-
    // iteration placement measured 10pp tensor% worse — R13).
    load_chunk(sb0, 0);
    CP_COMMIT;
    for (int ch = 0; ch < NCH; ch++) {
        const unsigned sb = sb0 + (unsigned)(ch & 1) * STAGE;
        CP_WAIT0;
        __syncthreads();
        compute_ks(sb, 0);
        if (ch + 1 < NCH) {
            load_chunk(sb0 + (unsigned)((ch + 1) & 1) * STAGE, (ch + 1) * BK);
            CP_COMMIT;
        }
        compute_ks(sb, 1);
    }

    const int mbase = m0 + wm * 64 + (lane >> 2);
    const int nbase = n0 + wn * 32 + 2 * (lane & 3);
    if (MODE == 0) {
        __nv_bfloat16* Hp = (z == 0) ? Qh : (z == 1) ? Kh : Vh;
        __nv_bfloat16* Lp = (z == 0) ? Ql : (z == 1) ? Kl : Vl;
        // q pre-scale folds softmax scale AND log2(e): 0.125 * 1.4426950408889634
        const float sc = (z == 0) ? 0.18033688511112043f : 1.0f;
        #pragma unroll
        for (int mt = 0; mt < 4; mt++) {
            #pragma unroll
            for (int nt = 0; nt < 4; nt++) {
                int m = mbase + mt * 16;
                int n = nbase + nt * 8;
                int h = n >> 6, d0 = n & 63;
                int b = m >> 11;
                size_t base = (((size_t)(b * H_ + h)) * S_ + (m & 2047)) * D_ + d0;
                #pragma unroll
                for (int half = 0; half < 2; half++) {
                    float v0 = acc[mt][nt][2 * half] * sc;
                    float v1 = acc[mt][nt][2 * half + 1] * sc;
                    __nv_bfloat16 h0, l0, h1, l1;
                    split1(v0, h0, l0);
                    split1(v1, h1, l1);
                    __nv_bfloat162 hv; hv.x = h0; hv.y = h1;
                    __nv_bfloat162 lv; lv.x = l0; lv.y = l1;
                    size_t a = base + (size_t)half * 8 * D_;
                    *(__nv_bfloat162*)(Hp + a) = hv;
                    *(__nv_bfloat162*)(Lp + a) = lv;
                }
            }
        }
    } else {
        #pragma unroll
        for (int mt = 0; mt < 4; mt++) {
            #pragma unroll
            for (int nt = 0; nt < 4; nt++) {
                int m = mbase + mt * 16;
                int n = nbase + nt * 8;
                size_t base = (size_t)m * E_ + n;
                *(float2*)(Of + base) = make_float2(acc[mt][nt][0], acc[mt][nt][1]);
                *(float2*)(Of + base + 8 * E_) = make_float2(acc[mt][nt][2], acc[mt][nt][3]);
            }
        }
    }
}

// ---------------- mma.sync flash attention (causal, bf16 split) ----------------
// Scores arrive in exp2 units (log2 e folded into Q); softmax uses ex2.approx.
#define AROWB 144                    // 72 bf16 per padded row
#define SQL   (128 * AROWB)          // 18432
#define SKV0  (2 * 128 * AROWB)      // 36864
#define KVSTAGE (4 * 64 * AROWB)     // KH,KL,VH,VL = 36864
#define KARR  (64 * AROWB)           // 9216 per sub-array
#define ATT_SMEM (SKV0 + 2 * KVSTAGE)  // 110592

__global__ __launch_bounds__(256, 2) void flash_mma(
    const __nv_bfloat16* __restrict__ Qh, const __nv_bfloat16* __restrict__ Ql,
    const __nv_bfloat16* __restrict__ Kh, const __nv_bfloat16* __restrict__ Kl,
    const __nv_bfloat16* __restrict__ Vh, const __nv_bfloat16* __restrict__ Vl,
    __nv_bfloat16* __restrict__ Ohi, __nv_bfloat16* __restrict__ Olo)
{
    extern __shared__ char smem[];
    const unsigned sb = smem_u32(smem);
    const int tid = threadIdx.x;
    const int lane = tid & 31, wq = tid >> 5;
    const int bx = gridDim.x - 1 - blockIdx.x;   // heavy blocks first
    const int bh = blockIdx.y;
    const int q0 = bx * 128;
    const size_t hb = (size_t)bh * S_ * D_;

    // Q tiles (hi+lo), loaded once: 2048 x 16B
    #pragma unroll
    for (int j = 0; j < 8; j++) {
        int id = tid + j * 256;
        int arr = id >> 10;
        int r = (id & 1023) >> 3, c = id & 7;
        unsigned off = (arr ? SQL : 0) + r * AROWB + c * 16;
        const __nv_bfloat16* src = (arr ? Ql : Qh) + hb + (size_t)(q0 + r) * D_ + c * 8;
        cpasync16(sb + off, src);
    }
    auto load_kv = [&](int stage, int kv0) {
        unsigned base = sb + SKV0 + (unsigned)stage * KVSTAGE;
        #pragma unroll
        for (int j = 0; j < 8; j++) {
            int id = tid + j * 256;
            int arr = id >> 9;       // 0 KH, 1 KL, 2 VH, 3 VL
            int r = (id & 511) >> 3, c = id & 7;
            unsigned off = (unsigned)arr * KARR + r * AROWB + c * 16;
            const __nv_bfloat16* src =
                (arr == 0 ? Kh : arr == 1 ? Kl : arr == 2 ? Vh : Vl)
                + hb + (size_t)(kv0 + r) * D_ + c * 8;
            cpasync16(base + off, src);
        }
    };

    const int nt = 2 * bx + 2;
    load_kv(0, 0);
    CP_COMMIT;

    float sacc[8][4], oacc[8][4];
    float mrow[2] = {-1e30f, -1e30f}, lrow[2] = {0.f, 0.f};
    #pragma unroll
    for (int j = 0; j < 8; j++)
        #pragma unroll
        for (int c = 0; c < 4; c++) oacc[j][c] = 0.f;

    const unsigned qoff = sb + (unsigned)((wq * 16 + (lane & 15)) * AROWB + (lane >> 4) * 16);
    const unsigned krow = (unsigned)((lane & 7) + ((lane >> 4) << 3));
    const unsigned kcolb = (unsigned)(((lane >> 3) & 1) * 16);
    const unsigned vrow = (unsigned)((lane & 7) + (((lane >> 3) & 1) << 3));
    const unsigned vcolb = (unsigned)((lane >> 4) * 16);
    const int rl0 = wq * 16 + (lane >> 2);

    for (int t0 = 0; t0 < nt; t0++) {
        const int kv0 = t0 * 64;
        const unsigned kvb = sb + SKV0 + (unsigned)(t0 & 1) * KVSTAGE;
        CP_WAIT0;
        __syncthreads();

        // last kv tile (kv0 = q0+64): warps covering rows < kv0 are fully
        // masked — skip their S/softmax/PV entirely. The load_kv below is
        // OUTSIDE this guard (uniform across warps), and no barrier or smem
        // write exists inside the guarded region.
        const bool active = !(t0 == nt - 1 && wq < 4);

        if (active) {
        // ---- S = Q K^T (3-product split, jj-pair interleaved) ----
        #pragma unroll
        for (int j = 0; j < 8; j++) {
            sacc[j][0] = 0.f; sacc[j][1] = 0.f; sacc[j][2] = 0.f; sacc[j][3] = 0.f;
        }
        #pragma unroll
        for (int ks = 0; ks < 4; ks++) {
            unsigned qh4[4], ql4[4];
            ldm_x4(qh4, qoff + ks * 32);
            ldm_x4(ql4, qoff + SQL + ks * 32);
            #pragma unroll
            for (int p = 0; p < 2; p++) {           // jj pairs (2p, 2p+1)
                unsigned b0h[4], b0l[4], b1h[4], b1l[4];
                unsigned ko0 = kvb + ((2 * p)     * 16 + krow) * AROWB + kcolb + ks * 32;
                unsigned ko1 = kvb + ((2 * p + 1) * 16 + krow) * AROWB + kcolb + ks * 32;
                ldm_x4(b0h, ko0);
                ldm_x4(b0l, ko0 + KARR);
                ldm_x4(b1h, ko1);
                ldm_x4(b1l, ko1 + KARR);
                float* a0 = sacc[4 * p + 0];
                float* a1 = sacc[4 * p + 1];
                float* a2 = sacc[4 * p + 2];
                float* a3 = sacc[4 * p + 3];
                mma_bf16(a0, qh4, b0h);     mma_bf16(a1, qh4, b0h + 2);
                mma_bf16(a2, qh4, b1h);     mma_bf16(a3, qh4, b1h + 2);
                mma_bf16(a0, qh4, b0l);     mma_bf16(a1, qh4, b0l + 2);
                mma_bf16(a2, qh4, b1l);     mma_bf16(a3, qh4, b1l + 2);
                mma_bf16(a0, ql4, b0h);     mma_bf16(a1, ql4, b0h + 2);
                mma_bf16(a2, ql4, b1h);     mma_bf16(a3, ql4, b1h + 2);
            }
        }
        } // active (S phase)

        // issue next tile's KV loads now — overlaps softmax + PV below
        if (t0 + 1 < nt) {
            load_kv((t0 + 1) & 1, kv0 + 64);
            CP_COMMIT;
        }

        if (active) {
        // ---- mask + online softmax (exp2 domain, MUFU) ----
        const bool maskt = (t0 >= nt - 2);
        const int rel = kv0 - q0;
        #pragma unroll
        for (int h = 0; h < 2; h++) {
            const int rloc = rl0 + 8 * h;
            if (maskt) {
                #pragma unroll
                for (int j = 0; j < 8; j++) {
                    int c0 = 8 * j + 2 * (lane & 3) + rel;
                    if (c0 > rloc)     sacc[j][2 * h]     = -1e30f;
                    if (c0 + 1 > rloc) sacc[j][2 * h + 1] = -1e30f;
                }
            }
            float mx = mrow[h];
            #pragma unroll
            for (int j = 0; j < 8; j++)
                mx = fmaxf(mx, fmaxf(sacc[j][2 * h], sacc[j][2 * h + 1]));
            mx = fmaxf(mx, __shfl_xor_sync(0xffffffffu, mx, 1));
            mx = fmaxf(mx, __shfl_xor_sync(0xffffffffu, mx, 2));
            float alpha = fexp2(mrow[h] - mx);
            mrow[h] = mx;
            float rs = 0.f;
            #pragma unroll
            for (int j = 0; j < 8; j++) {
                float p0 = fexp2(sacc[j][2 * h] - mx);
                float p1 = fexp2(sacc[j][2 * h + 1] - mx);
                sacc[j][2 * h] = p0; sacc[j][2 * h + 1] = p1;
                rs += p0 + p1;
            }
            rs += __shfl_xor_sync(0xffffffffu, rs, 1);
            rs += __shfl_xor_sync(0xffffffffu, rs, 2);
            lrow[h] = lrow[h] * alpha + rs;
            #pragma unroll
            for (int j = 0; j < 8; j++) {
                oacc[j][2 * h] *= alpha;
                oacc[j][2 * h + 1] *= alpha;
            }
        }

        // ---- O += P V (P in registers, g-pair interleaved) ----
        #pragma unroll
        for (int ks = 0; ks < 4; ks++) {
            unsigned phi[4], plo[4];
            #pragma unroll
            for (int i = 0; i < 4; i++) {
                int j = 2 * ks + (i >> 1);
                int bse = (i & 1) * 2;
                float p0 = sacc[j][bse], p1 = sacc[j][bse + 1];
                unsigned hp = pack_bf2(p0, p1);
                float2 hf = unpack_bf2(hp);
                phi[i] = hp;
                plo[i] = pack_bf2(p0 - hf.x, p1 - hf.y);
            }
            #pragma unroll
            for (int gp = 0; gp < 2; gp++) {        // g pairs (2gp, 2gp+1)
                unsigned vah[4], val[4], vbh2[4], vbl2[4];
                unsigned vo0 = kvb + 2 * KARR + (ks * 16 + vrow) * AROWB + vcolb + (2 * gp) * 32;
                unsigned vo1 = vo0 + 32;
                ldm_x4_t(vah, vo0);
                ldm_x4_t(val, vo0 + KARR);
                ldm_x4_t(vbh2, vo1);
                ldm_x4_t(vbl2, vo1 + KARR);
                float* o0 = oacc[4 * gp + 0];
                float* o1 = oacc[4 * gp + 1];
                float* o2 = oacc[4 * gp + 2];
                float* o3 = oacc[4 * gp + 3];
                mma_bf16(o0, phi, vah);     mma_bf16(o1, phi, vah + 2);
                mma_bf16(o2, phi, vbh2);    mma_bf16(o3, phi, vbh2 + 2);
                mma_bf16(o0, phi, val);     mma_bf16(o1, phi, val + 2);
                mma_bf16(o2, phi, vbl2);    mma_bf16(o3, phi, vbl2 + 2);
                mma_bf16(o0, plo, vah);     mma_bf16(o1, plo, vah + 2);
                mma_bf16(o2, plo, vbh2);    mma_bf16(o3, plo, vbh2 + 2);
            }
        }
        } // active (softmax+PV)
    }

    // ---- epilogue: O/l -> bf16 hi/lo, row-major (b*S+s, h*64+d) ----
    const int b = bh >> 4, hd = bh & 15;
    #pragma unroll
    for (int hh = 0; hh < 2; hh++) {
        float linv = 1.f / lrow[hh];
        int s = q0 + wq * 16 + (lane >> 2) + 8 * hh;
        size_t rowb = ((size_t)b * S_ + s) * E_ + hd * D_ + 2 * (lane & 3);
        #pragma unroll
        for (int j = 0; j < 8; j++) {
            float o0 = oacc[j][2 * hh] * linv;
            float o1 = oacc[j][2 * hh + 1] * linv;
            __nv_bfloat16 h0, l0, h1, l1;
            split1(o0, h0, l0);
            split1(o1, h1, l1);
            __nv_bfloat162 hv; hv.x = h0; hv.y = h1;
            __nv_bfloat162 lv; lv.x = l0; lv.y = l1;
            *(__nv_bfloat162*)(Ohi + rowb + 8 * j) = hv;
            *(__nv_bfloat162*)(Olo + rowb + 8 * j) = lv;
        }
    }
}

// ---------------- mod = silu(cond) @ Wc^T + bc ----------------
__global__ __launch_bounds__(256) void mod_kernel(
    const float* __restrict__ cond, const float* __restrict__ Wc,
    const float* __restrict__ bc, float* __restrict__ mod)
{
    __shared__ float sc[C_];
    int gid = blockIdx.x * 256 + threadIdx.x;
    int b = gid >> 11;
    int j = gid & 2047;
    {
        float c = cond[b * C_ + threadIdx.x];
        sc[threadIdx.x] = c / (1.f + __expf(-c));
    }
    __syncthreads();
    const float* wr = Wc + (size_t)j * C_;
    float acc = 0.f;
    #pragma unroll 8
    for (int c = 0; c < C_; c += 4) {
        float4 w = *(const float4*)&wr[c];
        acc += sc[c] * w.x + sc[c + 1] * w.y + sc[c + 2] * w.z + sc[c + 3] * w.w;
    }
    mod[gid] = acc + bc[j];
}

// ---------------- RMSNorm + FiLM ----------------
__global__ __launch_bounds__(256) void norm_film(
    const float* __restrict__ X, const float* __restrict__ gscale,
    const float* __restrict__ mod, float* __restrict__ out)
{
    const int m = blockIdx.x;
    const int b = m >> 11;
    const float* xr = X + (size_t)m * E_;
    const int e = threadIdx.x * 4;
    float4 v = *(const float4*)&xr[e];
    float ss = v.x * v.x + v.y * v.y + v.z * v.z + v.w * v.w;
    #pragma unroll
    for (int off = 16; off; off >>= 1)
        ss += __shfl_xor_sync(0xffffffffu, ss, off);
    __shared__ float red[8];
    if ((threadIdx.x & 31) == 0) red[threadIdx.x >> 5] = ss;
    __syncthreads();
    float tot = 0.f;
    #pragma unroll
    for (int i = 0; i < 8; i++) tot += red[i];
    float inv = rsqrtf(tot * (1.f / (float)E_) + 1e-6f);

    const float* mb = mod + (size_t)b * 2 * E_;
    float4 g  = *(const float4*)&gscale[e];
    float4 sh = *(const float4*)&mb[e];
    float4 sv = *(const float4*)&mb[E_ + e];
    float4 o;
    o.x = v.x * inv * g.x * (1.f + sv.x) + sh.x;
    o.y = v.y * inv * g.y * (1.f + sv.y) + sh.y;
    o.z = v.z * inv * g.z * (1.f + sv.z) + sh.z;
    o.w = v.w * inv * g.w * (1.f + sv.w) + sh.w;
    *(float4*)&out[(size_t)m * E_ + e] = o;
}

// ---------------- launch ----------------
extern "C" void kernel_launch(void* const* d_in, const int* in_sizes, int n_in,
                              void* d_out, int out_size)
{
    const float* x    = (const float*)d_in[0];
    // d_in[1] = mask: provably triu(ones,k=1) causal -> applied analytically
    const float* cond = (const float*)d_in[2];
    const float* Wq   = (const float*)d_in[3];
    const float* Wk   = (const float*)d_in[4];
    const float* Wv   = (const float*)d_in[5];
    const float* Wo   = (const float*)d_in[6];
    const float* rsc  = (const float*)d_in[7];
    const float* Wc   = (const float*)d_in[8];
    const float* bc   = (const float*)d_in[9];
    float* out = (float*)d_out;

    float *proj, *mod;
    __nv_bfloat16 *xhi, *xlo, *whi, *wlo, *ahi, *alo;
    __nv_bfloat16 *qh, *ql, *kh, *kl, *vh, *vl;
    cudaGetSymbolAddress((void**)&proj, g_proj);
    cudaGetSymbolAddress((void**)&mod,  g_mod);
    cudaGetSymbolAddress((void**)&xhi,  g_xhi);
    cudaGetSymbolAddress((void**)&xlo,  g_xlo);
    cudaGetSymbolAddress((void**)&whi,  g_whi);
    cudaGetSymbolAddress((void**)&wlo,  g_wlo);
    cudaGetSymbolAddress((void**)&ahi,  g_ahi);
    cudaGetSymbolAddress((void**)&alo,  g_alo);
    cudaGetSymbolAddress((void**)&qh,   g_qh);
    cudaGetSymbolAddress((void**)&ql,   g_ql);
    cudaGetSymbolAddress((void**)&kh,   g_kh);
    cudaGetSymbolAddress((void**)&kl,   g_kl);
    cudaGetSymbolAddress((void**)&vh,   g_vh);
    cudaGetSymbolAddress((void**)&vl,   g_vl);

    cudaFuncSetAttribute(gemm_mma<0>, cudaFuncAttributeMaxDynamicSharedMemorySize, GSM);
    cudaFuncSetAttribute(gemm_mma<1>, cudaFuncAttributeMaxDynamicSharedMemorySize, GSM);
    cudaFuncSetAttribute(flash_mma, cudaFuncAttributeMaxDynamicSharedMemorySize, ATT_SMEM);

    // fp32 -> bf16 hi/lo splits
    conv_split<<<M_TOT * E_ / 1024, 256>>>(x, xhi, xlo);
    conv_split_w<<<dim3(E_ * E_ / 1024, 1, 4), 256>>>(Wq, Wk, Wv, Wo, whi, wlo);
    // conditioning modulation (independent)
    mod_kernel<<<(B_ * 2 * E_) / 256, 256>>>(cond, Wc, bc, mod);
    // QKV projections -> bf16 hi/lo (B,H,S,D); q pre-scaled (incl. log2 e)
    gemm_mma<0><<<dim3(E_ / BN, M_TOT / BM, 3), 256, GSM>>>(
        xhi, xlo, whi, wlo, qh, ql, kh, kl, vh, vl, nullptr);
    // causal flash attention on tensor cores -> bf16 hi/lo (m, E)
    flash_mma<<<dim3(S_ / 128, B_ * H_), 256, ATT_SMEM>>>(
        qh, ql, kh, kl, vh, vl, ahi, alo);
    // output projection -> fp32
    gemm_mma<1><<<dim3(E_ / BN, M_TOT / BM, 1), 256, GSM>>>(
        ahi, alo, whi, wlo, nullptr, nullptr, nullptr, nullptr, nullptr, nullptr, proj);
    // RMSNorm + FiLM
    norm_film<<<M_TOT, 256>>>(proj, rsc, mod, out);
}